// round 1
// baseline (speedup 1.0000x reference)
#include <cuda_runtime.h>
#include <cuda_bf16.h>
#include <math.h>

// Problem constants
#define BATCH 8
#define NQ 1024
#define NKV 1024
#define DIM 1024
#define NHEADS 16
#define HDIM 64
#define MROWS (BATCH * NQ)   // 8192

// Scratch (device globals; no allocation allowed)
__device__ float g_Q[MROWS * DIM];
__device__ float g_K[MROWS * DIM];
__device__ float g_V[MROWS * DIM];
__device__ float g_O[MROWS * DIM];

// ---------------------------------------------------------------------------
// helpers
// ---------------------------------------------------------------------------
__device__ __forceinline__ void split2(float x, float y, unsigned &hi, unsigned &lo) {
    __nv_bfloat162 h = __floats2bfloat162_rn(x, y);            // .x = x (low), .y = y (high)
    float hx = __bfloat162float(h.x);
    float hy = __bfloat162float(h.y);
    __nv_bfloat162 l = __floats2bfloat162_rn(x - hx, y - hy);
    hi = *reinterpret_cast<unsigned*>(&h);
    lo = *reinterpret_cast<unsigned*>(&l);
}

__device__ __forceinline__ void mma16816(float* c, const unsigned* a, unsigned b0, unsigned b1) {
    asm volatile(
        "mma.sync.aligned.m16n8k16.row.col.f32.bf16.bf16.f32 "
        "{%0,%1,%2,%3}, {%4,%5,%6,%7}, {%8,%9}, {%0,%1,%2,%3};\n"
        : "+f"(c[0]), "+f"(c[1]), "+f"(c[2]), "+f"(c[3])
        : "r"(a[0]), "r"(a[1]), "r"(a[2]), "r"(a[3]), "r"(b0), "r"(b1));
}

// ---------------------------------------------------------------------------
// GEMM:  C[M=8192, N=1024] = A[M, K=1024] @ W[K, N] + bias
// block tile 128x128, K-tile 32, 8 warps (2x4), warp tile 64x32
// bf16 hi/lo split: acc += Ah*Bh + Ah*Bl + Al*Bh
// ---------------------------------------------------------------------------
__global__ __launch_bounds__(256) void gemm_bias_kernel(
    const float* __restrict__ A, const float* __restrict__ W,
    const float* __restrict__ bias, float* __restrict__ C)
{
    __shared__ unsigned As_hi[128][20];   // [m][kpair], stride 20 -> conflict-free frag loads
    __shared__ unsigned As_lo[128][20];
    __shared__ unsigned Bs_hi[128][20];   // [n][kpair]
    __shared__ unsigned Bs_lo[128][20];

    const int tid  = threadIdx.x;
    const int lane = tid & 31;
    const int warp = tid >> 5;
    const int grp  = lane >> 2;
    const int q4   = lane & 3;
    const int wm   = warp >> 2;   // 0..1
    const int wn   = warp & 3;    // 0..3

    const int m0 = blockIdx.y * 128;
    const int n0 = blockIdx.x * 128;

    float acc[4][4][4];
#pragma unroll
    for (int i = 0; i < 4; i++)
#pragma unroll
        for (int j = 0; j < 4; j++)
#pragma unroll
            for (int k = 0; k < 4; k++) acc[i][j][k] = 0.f;

    for (int k0 = 0; k0 < DIM; k0 += 32) {
        // ---- load A tile (128 x 32) as hi/lo bf16 pairs ----
#pragma unroll
        for (int i = 0; i < 8; i++) {
            int idx = tid + i * 256;          // 0..2047
            int m  = idx >> 4;
            int kp = idx & 15;
            float2 v = *reinterpret_cast<const float2*>(
                A + (size_t)(m0 + m) * DIM + k0 + kp * 2);
            split2(v.x, v.y, As_hi[m][kp], As_lo[m][kp]);
        }
        // ---- load W tile (32 x 128), packed along k per n ----
#pragma unroll
        for (int i = 0; i < 8; i++) {
            int idx = tid + i * 256;          // 0..2047
            int n  = idx & 127;
            int kp = idx >> 7;                // 0..15
            float w0 = W[(size_t)(k0 + 2 * kp)     * DIM + n0 + n];
            float w1 = W[(size_t)(k0 + 2 * kp + 1) * DIM + n0 + n];
            split2(w0, w1, Bs_hi[n][kp], Bs_lo[n][kp]);
        }
        __syncthreads();

#pragma unroll
        for (int kk = 0; kk < 2; kk++) {
            const int kb = kk * 8 + q4;
            unsigned ah[4][4], al[4][4];
#pragma unroll
            for (int mi = 0; mi < 4; mi++) {
                int r = wm * 64 + mi * 16 + grp;
                ah[mi][0] = As_hi[r][kb];     ah[mi][1] = As_hi[r + 8][kb];
                ah[mi][2] = As_hi[r][kb + 4]; ah[mi][3] = As_hi[r + 8][kb + 4];
                al[mi][0] = As_lo[r][kb];     al[mi][1] = As_lo[r + 8][kb];
                al[mi][2] = As_lo[r][kb + 4]; al[mi][3] = As_lo[r + 8][kb + 4];
            }
            unsigned bh[4][2], bl[4][2];
#pragma unroll
            for (int ni = 0; ni < 4; ni++) {
                int n = wn * 32 + ni * 8 + grp;
                bh[ni][0] = Bs_hi[n][kb]; bh[ni][1] = Bs_hi[n][kb + 4];
                bl[ni][0] = Bs_lo[n][kb]; bl[ni][1] = Bs_lo[n][kb + 4];
            }
#pragma unroll
            for (int mi = 0; mi < 4; mi++) {
#pragma unroll
                for (int ni = 0; ni < 4; ni++) {
                    mma16816(acc[mi][ni], ah[mi], bh[ni][0], bh[ni][1]);
                    mma16816(acc[mi][ni], ah[mi], bl[ni][0], bl[ni][1]);
                    mma16816(acc[mi][ni], al[mi], bh[ni][0], bh[ni][1]);
                }
            }
        }
        __syncthreads();
    }

    // epilogue
#pragma unroll
    for (int mi = 0; mi < 4; mi++) {
        int row = m0 + wm * 64 + mi * 16 + grp;
#pragma unroll
        for (int ni = 0; ni < 4; ni++) {
            int col = n0 + wn * 32 + ni * 8 + 2 * q4;
            float b0 = bias[col], b1 = bias[col + 1];
            float2 v0 = make_float2(acc[mi][ni][0] + b0, acc[mi][ni][1] + b1);
            float2 v1 = make_float2(acc[mi][ni][2] + b0, acc[mi][ni][3] + b1);
            *reinterpret_cast<float2*>(C + (size_t)row * DIM + col)       = v0;
            *reinterpret_cast<float2*>(C + (size_t)(row + 8) * DIM + col) = v1;
        }
    }
}

// ---------------------------------------------------------------------------
// Flash attention: per block (q-tile of 128 rows, one (b,h)); kv-tile = 128.
// S = (Q*scale) K^T with bf16x3; online softmax fp32; O += P V with bf16x3
// (P kept in registers via the C-fragment -> A-fragment layout identity).
// ---------------------------------------------------------------------------
#define ATTN_SMEM_WORDS (4 * 128 * 36 + 2 * 64 * 68)
#define ATTN_SMEM_BYTES (ATTN_SMEM_WORDS * 4)

__global__ __launch_bounds__(256) void attn_kernel(
    const float* __restrict__ Q, const float* __restrict__ Kb,
    const float* __restrict__ Vb, float* __restrict__ O)
{
    extern __shared__ unsigned smbuf[];
    unsigned (*Qh)[36] = reinterpret_cast<unsigned(*)[36]>(smbuf);
    unsigned (*Ql)[36] = reinterpret_cast<unsigned(*)[36]>(smbuf + 128 * 36);
    unsigned (*Kh)[36] = reinterpret_cast<unsigned(*)[36]>(smbuf + 2 * 128 * 36);
    unsigned (*Kl)[36] = reinterpret_cast<unsigned(*)[36]>(smbuf + 3 * 128 * 36);
    unsigned (*Vh)[68] = reinterpret_cast<unsigned(*)[68]>(smbuf + 4 * 128 * 36);
    unsigned (*Vl)[68] = reinterpret_cast<unsigned(*)[68]>(smbuf + 4 * 128 * 36 + 64 * 68);

    const int tid  = threadIdx.x;
    const int lane = tid & 31;
    const int warp = tid >> 5;
    const int grp  = lane >> 2;
    const int q4   = lane & 3;

    const int bh = blockIdx.y;
    const int b  = bh >> 4;
    const int h  = bh & 15;
    const int q0 = blockIdx.x * 128;
    const float scale = 0.125f;  // 1/sqrt(64)

    // ---- load Q tile (scaled) ----
    const float* Qbase = Q + ((size_t)(b * NQ + q0)) * DIM + h * HDIM;
#pragma unroll
    for (int i = 0; i < 16; i++) {
        int idx = tid + i * 256;          // 0..4095
        int r  = idx >> 5;
        int dp = idx & 31;
        float2 v = *reinterpret_cast<const float2*>(Qbase + (size_t)r * DIM + dp * 2);
        v.x *= scale; v.y *= scale;
        split2(v.x, v.y, Qh[r][dp], Ql[r][dp]);
    }

    float m0s = -1e30f, m1s = -1e30f;
    float l0 = 0.f, l1 = 0.f;
    float o[8][4];
#pragma unroll
    for (int i = 0; i < 8; i++)
#pragma unroll
        for (int j = 0; j < 4; j++) o[i][j] = 0.f;

    const int r = warp * 16 + grp;

    for (int kv0 = 0; kv0 < NKV; kv0 += 128) {
        __syncthreads();   // smem (K/V) free to overwrite; also publishes Q on first iter
        const float* Kbase = Kb + ((size_t)(b * NKV + kv0)) * DIM + h * HDIM;
#pragma unroll
        for (int i = 0; i < 16; i++) {
            int idx = tid + i * 256;
            int rr = idx >> 5;
            int dp = idx & 31;
            float2 v = *reinterpret_cast<const float2*>(Kbase + (size_t)rr * DIM + dp * 2);
            split2(v.x, v.y, Kh[rr][dp], Kl[rr][dp]);
        }
        const float* Vbase = Vb + ((size_t)(b * NKV + kv0)) * DIM + h * HDIM;
#pragma unroll
        for (int i = 0; i < 16; i++) {
            int idx = tid + i * 256;
            int d  = idx & 63;
            int kp = idx >> 6;            // 0..63 (kv pair)
            float v0 = Vbase[(size_t)(2 * kp)     * DIM + d];
            float v1 = Vbase[(size_t)(2 * kp + 1) * DIM + d];
            split2(v0, v1, Vh[d][kp], Vl[d][kp]);
        }
        __syncthreads();

        // ---- S = Q K^T (128 kv cols per warp-row-tile) ----
        float s[16][4];
#pragma unroll
        for (int i = 0; i < 16; i++)
#pragma unroll
            for (int j = 0; j < 4; j++) s[i][j] = 0.f;

#pragma unroll
        for (int dk = 0; dk < 4; dk++) {
            const int kb = dk * 8 + q4;
            unsigned qh[4], ql[4];
            qh[0] = Qh[r][kb];     qh[1] = Qh[r + 8][kb];
            qh[2] = Qh[r][kb + 4]; qh[3] = Qh[r + 8][kb + 4];
            ql[0] = Ql[r][kb];     ql[1] = Ql[r + 8][kb];
            ql[2] = Ql[r][kb + 4]; ql[3] = Ql[r + 8][kb + 4];
#pragma unroll
            for (int ni = 0; ni < 16; ni++) {
                int n = ni * 8 + grp;
                unsigned kh0 = Kh[n][kb], kh1 = Kh[n][kb + 4];
                unsigned kl0 = Kl[n][kb], kl1 = Kl[n][kb + 4];
                mma16816(s[ni], qh, kh0, kh1);
                mma16816(s[ni], qh, kl0, kl1);
                mma16816(s[ni], ql, kh0, kh1);
            }
        }

        // ---- online softmax ----
        float mx0 = -1e30f, mx1 = -1e30f;
#pragma unroll
        for (int ni = 0; ni < 16; ni++) {
            mx0 = fmaxf(mx0, fmaxf(s[ni][0], s[ni][1]));
            mx1 = fmaxf(mx1, fmaxf(s[ni][2], s[ni][3]));
        }
        mx0 = fmaxf(mx0, __shfl_xor_sync(0xffffffffu, mx0, 1));
        mx0 = fmaxf(mx0, __shfl_xor_sync(0xffffffffu, mx0, 2));
        mx1 = fmaxf(mx1, __shfl_xor_sync(0xffffffffu, mx1, 1));
        mx1 = fmaxf(mx1, __shfl_xor_sync(0xffffffffu, mx1, 2));

        float nm0 = fmaxf(m0s, mx0), nm1 = fmaxf(m1s, mx1);
        float f0 = __expf(m0s - nm0), f1 = __expf(m1s - nm1);
        m0s = nm0; m1s = nm1;

        float sum0 = 0.f, sum1 = 0.f;
#pragma unroll
        for (int ni = 0; ni < 16; ni++) {
            s[ni][0] = __expf(s[ni][0] - nm0); sum0 += s[ni][0];
            s[ni][1] = __expf(s[ni][1] - nm0); sum0 += s[ni][1];
            s[ni][2] = __expf(s[ni][2] - nm1); sum1 += s[ni][2];
            s[ni][3] = __expf(s[ni][3] - nm1); sum1 += s[ni][3];
        }
        sum0 += __shfl_xor_sync(0xffffffffu, sum0, 1);
        sum0 += __shfl_xor_sync(0xffffffffu, sum0, 2);
        sum1 += __shfl_xor_sync(0xffffffffu, sum1, 1);
        sum1 += __shfl_xor_sync(0xffffffffu, sum1, 2);
        l0 = l0 * f0 + sum0;
        l1 = l1 * f1 + sum1;

#pragma unroll
        for (int ni = 0; ni < 8; ni++) {
            o[ni][0] *= f0; o[ni][1] *= f0;
            o[ni][2] *= f1; o[ni][3] *= f1;
        }

        // ---- O += P @ V ----
#pragma unroll
        for (int st = 0; st < 8; st++) {
            const int t0 = 2 * st, t1 = t0 + 1;
            unsigned ph[4], pl[4];
            split2(s[t0][0], s[t0][1], ph[0], pl[0]);
            split2(s[t0][2], s[t0][3], ph[1], pl[1]);
            split2(s[t1][0], s[t1][1], ph[2], pl[2]);
            split2(s[t1][2], s[t1][3], ph[3], pl[3]);
            const int kp = st * 8 + q4;
#pragma unroll
            for (int ni = 0; ni < 8; ni++) {
                int n = ni * 8 + grp;
                unsigned vh0 = Vh[n][kp], vh1 = Vh[n][kp + 4];
                unsigned vl0 = Vl[n][kp], vl1 = Vl[n][kp + 4];
                mma16816(o[ni], ph, vh0, vh1);
                mma16816(o[ni], ph, vl0, vl1);
                mma16816(o[ni], pl, vh0, vh1);
            }
        }
    }

    // ---- epilogue ----
    float inv0 = 1.f / l0, inv1 = 1.f / l1;
    const int r0 = q0 + warp * 16 + grp;
    float* Ob = O + ((size_t)b * NQ) * DIM + h * HDIM;
#pragma unroll
    for (int ni = 0; ni < 8; ni++) {
        int c = ni * 8 + 2 * q4;
        float2 v0 = make_float2(o[ni][0] * inv0, o[ni][1] * inv0);
        float2 v1 = make_float2(o[ni][2] * inv1, o[ni][3] * inv1);
        *reinterpret_cast<float2*>(Ob + (size_t)r0 * DIM + c)       = v0;
        *reinterpret_cast<float2*>(Ob + (size_t)(r0 + 8) * DIM + c) = v1;
    }
}

// ---------------------------------------------------------------------------
// launch
// ---------------------------------------------------------------------------
extern "C" void kernel_launch(void* const* d_in, const int* in_sizes, int n_in,
                              void* d_out, int out_size)
{
    (void)in_sizes; (void)n_in; (void)out_size;
    const float* x   = (const float*)d_in[0];
    const float* ctx = (const float*)d_in[1];
    const float* Wq  = (const float*)d_in[2];
    const float* bq  = (const float*)d_in[3];
    const float* Wk  = (const float*)d_in[4];
    const float* bk  = (const float*)d_in[5];
    const float* Wv  = (const float*)d_in[6];
    const float* bv  = (const float*)d_in[7];
    const float* Wo  = (const float*)d_in[8];
    const float* bo  = (const float*)d_in[9];
    float* out = (float*)d_out;

    float *pQ, *pK, *pV, *pO;
    cudaGetSymbolAddress((void**)&pQ, g_Q);
    cudaGetSymbolAddress((void**)&pK, g_K);
    cudaGetSymbolAddress((void**)&pV, g_V);
    cudaGetSymbolAddress((void**)&pO, g_O);

    cudaFuncSetAttribute(attn_kernel,
                         cudaFuncAttributeMaxDynamicSharedMemorySize,
                         ATTN_SMEM_BYTES);

    dim3 gblk(256);
    dim3 ggrid(DIM / 128, MROWS / 128);   // (8, 64)

    gemm_bias_kernel<<<ggrid, gblk>>>(x,   Wq, bq, pQ);
    gemm_bias_kernel<<<ggrid, gblk>>>(ctx, Wk, bk, pK);
    gemm_bias_kernel<<<ggrid, gblk>>>(ctx, Wv, bv, pV);

    attn_kernel<<<dim3(NQ / 128, BATCH * NHEADS), 256, ATTN_SMEM_BYTES>>>(pQ, pK, pV, pO);

    gemm_bias_kernel<<<ggrid, gblk>>>(pO, Wo, bo, out);
}